// round 2
// baseline (speedup 1.0000x reference)
#include <cuda_runtime.h>
#include <climits>

// Problem constants
#define B_ROWS   4096
#define N_COLS   8192
#define H_HALF   4096           // N/2
#define N_HALVES (B_ROWS * 2)   // 8192 row-halves
#define THREADS  256
#define F4_PER_HALF (H_HALF / 4)               // 1024 float4 per half
#define F4_PER_THREAD (F4_PER_HALF / THREADS)  // 4

// Deterministic scratch: per-row-half loss
__device__ float g_half_loss[N_HALVES];

__global__ void __launch_bounds__(THREADS, 8)
pulse_half_loss_kernel(const float* __restrict__ pred,
                       const float* __restrict__ lab)
{
    const int bh   = blockIdx.x;              // 0 .. N_HALVES-1
    const int row  = bh >> 1;
    const int half = bh & 1;
    const long base = (long)row * N_COLS + (long)half * H_HALF;

    const float4* __restrict__ p4 = reinterpret_cast<const float4*>(pred + base);
    const float4* __restrict__ l4 = reinterpret_cast<const float4*>(lab  + base);

    const int t = threadIdx.x;

    float sq[F4_PER_THREAD * 4];   // register-resident squared diffs
    float sse = 0.0f;
    int   mn  = INT_MAX;
    int   mx  = -1;

    // ---- Pass 1: streaming loads (data touched once; don't pollute L2),
    //      square diffs, min/max significant index
    #pragma unroll
    for (int k = 0; k < F4_PER_THREAD; k++) {
        const int i4 = t + k * THREADS;     // float4 index within the half
        const float4 p = __ldcs(&p4[i4]);
        const float4 l = __ldcs(&l4[i4]);
        const int e0 = i4 * 4;

        float d0 = p.x - l.x, d1 = p.y - l.y, d2 = p.z - l.z, d3 = p.w - l.w;
        float s0 = d0 * d0, s1 = d1 * d1, s2 = d2 * d2, s3 = d3 * d3;
        sq[k*4+0] = s0; sq[k*4+1] = s1; sq[k*4+2] = s2; sq[k*4+3] = s3;
        sse += (s0 + s1) + (s2 + s3);

        if (fabsf(l.x) > 0.01f) { mn = min(mn, e0 + 0); mx = max(mx, e0 + 0); }
        if (fabsf(l.y) > 0.01f) { mn = min(mn, e0 + 1); mx = max(mx, e0 + 1); }
        if (fabsf(l.z) > 0.01f) { mn = min(mn, e0 + 2); mx = max(mx, e0 + 2); }
        if (fabsf(l.w) > 0.01f) { mn = min(mn, e0 + 3); mx = max(mx, e0 + 3); }
    }

    // ---- Block min/max reduction for first/last significant index
    __shared__ int   s_mn[THREADS / 32];
    __shared__ int   s_mx[THREADS / 32];
    __shared__ float s_sum[THREADS / 32];
    __shared__ int   s_first, s_last;

    #pragma unroll
    for (int o = 16; o > 0; o >>= 1) {
        mn = min(mn, __shfl_down_sync(0xffffffffu, mn, o));
        mx = max(mx, __shfl_down_sync(0xffffffffu, mx, o));
    }
    const int lane = t & 31;
    const int warp = t >> 5;
    if (lane == 0) { s_mn[warp] = mn; s_mx[warp] = mx; }
    __syncthreads();
    if (t == 0) {
        int m0 = s_mn[0], m1 = s_mx[0];
        #pragma unroll
        for (int i = 1; i < THREADS / 32; i++) {
            m0 = min(m0, s_mn[i]);
            m1 = max(m1, s_mx[i]);
        }
        if (m1 < 0) { m0 = 0; m1 = H_HALF - 1; }   // all-insignificant fallback
        s_first = m0;
        s_last  = m1;
    }
    __syncthreads();
    const int first = s_first;
    const int last  = s_last;

    // ---- Pass 2 (registers only): add extra (penalty-1 = 1.0) for outside elems
    float extra = 0.0f;
    #pragma unroll
    for (int k = 0; k < F4_PER_THREAD; k++) {
        const int e0 = (t + k * THREADS) * 4;
        #pragma unroll
        for (int j = 0; j < 4; j++) {
            const int e = e0 + j;
            if (e < first || e > last) extra += sq[k*4+j];
        }
    }

    // ---- Block sum reduction of (sse + extra)
    float tot = sse + extra;
    #pragma unroll
    for (int o = 16; o > 0; o >>= 1)
        tot += __shfl_down_sync(0xffffffffu, tot, o);
    if (lane == 0) s_sum[warp] = tot;
    __syncthreads();
    if (t == 0) {
        float acc = s_sum[0];
        #pragma unroll
        for (int i = 1; i < THREADS / 32; i++) acc += s_sum[i];
        g_half_loss[bh] = acc * (1.0f / (float)H_HALF);
    }
}

// Final deterministic reduction: 8192 partials -> scalar / B
__global__ void __launch_bounds__(1024, 1)
pulse_final_reduce_kernel(float* __restrict__ out)
{
    const int t = threadIdx.x;
    float v = 0.0f;
    #pragma unroll
    for (int k = 0; k < N_HALVES / 1024; k++)
        v += g_half_loss[t + k * 1024];

    #pragma unroll
    for (int o = 16; o > 0; o >>= 1)
        v += __shfl_down_sync(0xffffffffu, v, o);

    __shared__ float s_sum[32];
    const int lane = t & 31, warp = t >> 5;
    if (lane == 0) s_sum[warp] = v;
    __syncthreads();
    if (t == 0) {
        float acc = s_sum[0];
        #pragma unroll
        for (int i = 1; i < 32; i++) acc += s_sum[i];
        out[0] = acc * (1.0f / (float)B_ROWS);
    }
}

extern "C" void kernel_launch(void* const* d_in, const int* in_sizes, int n_in,
                              void* d_out, int out_size)
{
    const float* pred = (const float*)d_in[0];
    const float* lab  = (const float*)d_in[1];
    float* out = (float*)d_out;

    pulse_half_loss_kernel<<<N_HALVES, THREADS>>>(pred, lab);
    pulse_final_reduce_kernel<<<1, 1024>>>(out);
}

// round 10
// speedup vs baseline: 1.0027x; 1.0027x over previous
#include <cuda_runtime.h>
#include <climits>

// Problem constants
#define B_ROWS   4096
#define N_COLS   8192
#define H_HALF   4096           // N/2
#define N_HALVES (B_ROWS * 2)   // 8192 row-halves
#define THREADS  256
#define F4_PER_HALF (H_HALF / 4)               // 1024 float4 per half
#define F4_PER_THREAD (F4_PER_HALF / THREADS)  // 4

#define FIXED_SCALE 4294967296.0   // 2^32

// Deterministic fixed-point accumulator + completion ticket.
// Reset to 0 by the last block each launch, so graph replays are clean.
__device__ unsigned long long g_acc  = 0ULL;
__device__ unsigned int       g_done = 0u;

__global__ void __launch_bounds__(THREADS, 4)
pulse_loss_kernel(const float* __restrict__ pred,
                  const float* __restrict__ lab,
                  float* __restrict__ out)
{
    const int bh   = blockIdx.x;              // 0 .. N_HALVES-1
    const int row  = bh >> 1;
    const int half = bh & 1;
    const long base = (long)row * N_COLS + (long)half * H_HALF;

    const float4* __restrict__ p4 = reinterpret_cast<const float4*>(pred + base);
    const float4* __restrict__ l4 = reinterpret_cast<const float4*>(lab  + base);

    const int t = threadIdx.x;

    float sq[F4_PER_THREAD * 4];   // register-resident squared diffs
    float sse = 0.0f;
    int   mn  = INT_MAX;
    int   mx  = -1;

    // ---- Pass 1: streaming 128-bit loads (touched once -> evict-first),
    //      squared diffs, min/max significant index
    #pragma unroll
    for (int k = 0; k < F4_PER_THREAD; k++) {
        const int i4 = t + k * THREADS;     // float4 index within the half
        const float4 p = __ldcs(&p4[i4]);
        const float4 l = __ldcs(&l4[i4]);
        const int e0 = i4 * 4;

        float d0 = p.x - l.x, d1 = p.y - l.y, d2 = p.z - l.z, d3 = p.w - l.w;
        float s0 = d0 * d0, s1 = d1 * d1, s2 = d2 * d2, s3 = d3 * d3;
        sq[k*4+0] = s0; sq[k*4+1] = s1; sq[k*4+2] = s2; sq[k*4+3] = s3;
        sse += (s0 + s1) + (s2 + s3);

        if (fabsf(l.x) > 0.01f) { mn = min(mn, e0 + 0); mx = max(mx, e0 + 0); }
        if (fabsf(l.y) > 0.01f) { mn = min(mn, e0 + 1); mx = max(mx, e0 + 1); }
        if (fabsf(l.z) > 0.01f) { mn = min(mn, e0 + 2); mx = max(mx, e0 + 2); }
        if (fabsf(l.w) > 0.01f) { mn = min(mn, e0 + 3); mx = max(mx, e0 + 3); }
    }

    // ---- Block min/max reduction for first/last significant index
    __shared__ int   s_mn[THREADS / 32];
    __shared__ int   s_mx[THREADS / 32];
    __shared__ float s_sum[THREADS / 32];
    __shared__ int   s_first, s_last;

    #pragma unroll
    for (int o = 16; o > 0; o >>= 1) {
        mn = min(mn, __shfl_down_sync(0xffffffffu, mn, o));
        mx = max(mx, __shfl_down_sync(0xffffffffu, mx, o));
    }
    const int lane = t & 31;
    const int warp = t >> 5;
    if (lane == 0) { s_mn[warp] = mn; s_mx[warp] = mx; }
    __syncthreads();
    if (t == 0) {
        int m0 = s_mn[0], m1 = s_mx[0];
        #pragma unroll
        for (int i = 1; i < THREADS / 32; i++) {
            m0 = min(m0, s_mn[i]);
            m1 = max(m1, s_mx[i]);
        }
        if (m1 < 0) { m0 = 0; m1 = H_HALF - 1; }   // all-insignificant fallback
        s_first = m0;
        s_last  = m1;
    }
    __syncthreads();
    const int first = s_first;
    const int last  = s_last;

    // ---- Pass 2 (registers only): weight 2.0 outside [first,last]
    //      => add sq once more for outside elements
    float extra = 0.0f;
    #pragma unroll
    for (int k = 0; k < F4_PER_THREAD; k++) {
        const int e0 = (t + k * THREADS) * 4;
        #pragma unroll
        for (int j = 0; j < 4; j++) {
            const int e = e0 + j;
            if (e < first || e > last) extra += sq[k*4+j];
        }
    }

    // ---- Block sum reduction of (sse + extra)
    float tot = sse + extra;
    #pragma unroll
    for (int o = 16; o > 0; o >>= 1)
        tot += __shfl_down_sync(0xffffffffu, tot, o);
    if (lane == 0) s_sum[warp] = tot;
    __syncthreads();

    // ---- Deterministic global accumulation (fixed-point integer atomics)
    //      + last-block finalize. No second kernel needed.
    if (t == 0) {
        float acc = s_sum[0];
        #pragma unroll
        for (int i = 1; i < THREADS / 32; i++) acc += s_sum[i];

        const double half_loss = (double)acc * (1.0 / (double)H_HALF);
        const unsigned long long q =
            (unsigned long long)__double2ll_rn(half_loss * FIXED_SCALE);
        atomicAdd(&g_acc, q);
        __threadfence();

        const unsigned int ticket = atomicAdd(&g_done, 1u);
        if (ticket == (unsigned int)(N_HALVES - 1)) {
            // All blocks have accumulated (their g_acc adds precede their
            // g_done adds via the fence). Read coherently, finalize, reset.
            const unsigned long long total = atomicAdd(&g_acc, 0ULL);
            out[0] = (float)((double)total * (1.0 / FIXED_SCALE)
                             * (1.0 / (double)B_ROWS));
            g_acc  = 0ULL;
            g_done = 0u;
            __threadfence();
        }
    }
}

extern "C" void kernel_launch(void* const* d_in, const int* in_sizes, int n_in,
                              void* d_out, int out_size)
{
    const float* pred = (const float*)d_in[0];
    const float* lab  = (const float*)d_in[1];
    float* out = (float*)d_out;

    pulse_loss_kernel<<<N_HALVES, THREADS>>>(pred, lab, out);
}